// round 1
// baseline (speedup 1.0000x reference)
#include <cuda_runtime.h>
#include <math.h>

#define BATCH 2
#define SEQ   2048
#define DM    1024
#define NH    16
#define DH    64

// Scratch (allocation-free rule: __device__ globals)
__device__ float g_qh[BATCH * NH * SEQ * DH];   // [b,h,s,d]
__device__ float g_kh[BATCH * NH * SEQ * DH];
__device__ float g_vh[BATCH * NH * SEQ * DH];
__device__ float g_att[BATCH * SEQ * DM];       // [b*s, h*64+d]

// ---------------------------------------------------------------------------
// GEMM: C = A[M,K] @ W[K,N] + bias.  MODE 0: row-major out. MODE 1: head layout.
// Block 128x128, K-tile 16, 256 threads, 8x8 micro-tile.
// ---------------------------------------------------------------------------
template <int MODE>
__global__ __launch_bounds__(256) void gemm_bias_k(
    const float* __restrict__ A, const float* __restrict__ W,
    const float* __restrict__ bias, float* __restrict__ C,
    int M, int N, int K)
{
    __shared__ __align__(16) float As[16][132];
    __shared__ __align__(16) float Bs[16][128];

    const int tid = threadIdx.x;
    const int tx = tid & 15, ty = tid >> 4;
    const int mbase = blockIdx.y * 128;
    const int nbase = blockIdx.x * 128;

    float acc[8][8];
#pragma unroll
    for (int i = 0; i < 8; i++)
#pragma unroll
        for (int j = 0; j < 8; j++) acc[i][j] = 0.f;

    for (int kt = 0; kt < K; kt += 16) {
        __syncthreads();
#pragma unroll
        for (int p = 0; p < 2; p++) {
            int f = p * 256 + tid;
            int ar = f >> 2, ac4 = f & 3;
            float4 v = *(const float4*)&A[(size_t)(mbase + ar) * K + kt + ac4 * 4];
            As[ac4 * 4 + 0][ar] = v.x;
            As[ac4 * 4 + 1][ar] = v.y;
            As[ac4 * 4 + 2][ar] = v.z;
            As[ac4 * 4 + 3][ar] = v.w;
        }
#pragma unroll
        for (int p = 0; p < 2; p++) {
            int f = p * 256 + tid;
            int br = f >> 5, bc4 = f & 31;
            *(float4*)&Bs[br][bc4 * 4] =
                *(const float4*)&W[(size_t)(kt + br) * N + nbase + bc4 * 4];
        }
        __syncthreads();
#pragma unroll
        for (int kk = 0; kk < 16; kk++) {
            float a[8], b[8];
            *(float4*)&a[0] = *(const float4*)&As[kk][ty * 8];
            *(float4*)&a[4] = *(const float4*)&As[kk][ty * 8 + 4];
            *(float4*)&b[0] = *(const float4*)&Bs[kk][tx * 8];
            *(float4*)&b[4] = *(const float4*)&Bs[kk][tx * 8 + 4];
#pragma unroll
            for (int i = 0; i < 8; i++)
#pragma unroll
                for (int j = 0; j < 8; j++)
                    acc[i][j] = fmaf(a[i], b[j], acc[i][j]);
        }
    }

#pragma unroll
    for (int i = 0; i < 8; i++) {
        int m = mbase + ty * 8 + i;
#pragma unroll
        for (int jb = 0; jb < 8; jb += 4) {
            int n = nbase + tx * 8 + jb;
            float4 v;
            v.x = acc[i][jb + 0] + bias[n + 0];
            v.y = acc[i][jb + 1] + bias[n + 1];
            v.z = acc[i][jb + 2] + bias[n + 2];
            v.w = acc[i][jb + 3] + bias[n + 3];
            if (MODE == 0) {
                *(float4*)&C[(size_t)m * N + n] = v;
            } else {
                int b_ = m >> 11, s_ = m & 2047;
                int h_ = n >> 6, d_ = n & 63;
                *(float4*)&C[(((size_t)(b_ * NH + h_)) * SEQ + s_) * DH + d_] = v;
            }
        }
    }
}

// ---------------------------------------------------------------------------
// Flash attention, fp32, causal, UNSCALED scores (keras Attention default).
// Block: 128 query rows, k-tiles of 128. 256 threads.
//   S-tile micro: 8 rows (ty) x 8 cols (tx), O micro: 8 rows x 4 d-cols.
// Dynamic smem: QsT[64][132] KsT[64][132] Vs[128][68] Ps[128][132]
// ---------------------------------------------------------------------------
#define SM_FLOATS (2 * 64 * 132 + 128 * 68 + 128 * 132)
#define SM_BYTES  (SM_FLOATS * 4)

__global__ __launch_bounds__(256, 1) void attn_k(
    const float* __restrict__ Qh, const float* __restrict__ Kh,
    const float* __restrict__ Vh, float* __restrict__ Out)
{
    extern __shared__ __align__(16) float sm[];
    float* QsT = sm;                       // [64][132]
    float* KsT = sm + 64 * 132;            // [64][132]
    float* Vs  = sm + 2 * 64 * 132;        // [128][68]
    float* Ps  = sm + 2 * 64 * 132 + 128 * 68;  // [128][132]

    const int tid = threadIdx.x;
    const int tx = tid & 15, ty = tid >> 4;
    const int qt = blockIdx.x;
    const int h  = blockIdx.y;
    const int b  = blockIdx.z;
    const size_t base = ((size_t)(b * NH + h)) * SEQ * DH;
    const int qbase = qt * 128;

    // Q tile -> transposed smem (lanes walk rows -> conflict-free scalar STS)
#pragma unroll
    for (int p = 0; p < 8; p++) {
        int f = p * 256 + tid;
        int r = f & 127, c4 = f >> 7;
        float4 v = *(const float4*)&Qh[base + (size_t)(qbase + r) * DH + c4 * 4];
        QsT[(c4 * 4 + 0) * 132 + r] = v.x;
        QsT[(c4 * 4 + 1) * 132 + r] = v.y;
        QsT[(c4 * 4 + 2) * 132 + r] = v.z;
        QsT[(c4 * 4 + 3) * 132 + r] = v.w;
    }

    float O[8][4];
    float mrow[8], lrow[8];
#pragma unroll
    for (int i = 0; i < 8; i++) {
        mrow[i] = -INFINITY; lrow[i] = 0.f;
#pragma unroll
        for (int j = 0; j < 4; j++) O[i][j] = 0.f;
    }

    for (int kt = 0; kt <= qt; kt++) {
        const int kbase = kt * 128;
        __syncthreads();  // prior PV reads of Ps/Vs done; QsT ready (1st iter)
#pragma unroll
        for (int p = 0; p < 8; p++) {
            int f = p * 256 + tid;
            int r = f & 127, c4 = f >> 7;
            float4 v = *(const float4*)&Kh[base + (size_t)(kbase + r) * DH + c4 * 4];
            KsT[(c4 * 4 + 0) * 132 + r] = v.x;
            KsT[(c4 * 4 + 1) * 132 + r] = v.y;
            KsT[(c4 * 4 + 2) * 132 + r] = v.z;
            KsT[(c4 * 4 + 3) * 132 + r] = v.w;
        }
#pragma unroll
        for (int p = 0; p < 8; p++) {
            int f = p * 256 + tid;
            int r = f >> 4, c4 = f & 15;
            *(float4*)&Vs[r * 68 + c4 * 4] =
                *(const float4*)&Vh[base + (size_t)(kbase + r) * DH + c4 * 4];
        }
        __syncthreads();

        // S = Q @ K^T  (128x128 tile, UNSCALED)
        float acc[8][8];
#pragma unroll
        for (int i = 0; i < 8; i++)
#pragma unroll
            for (int j = 0; j < 8; j++) acc[i][j] = 0.f;

#pragma unroll 4
        for (int dd = 0; dd < 64; dd++) {
            float a[8], bb[8];
            *(float4*)&a[0]  = *(const float4*)&QsT[dd * 132 + ty * 8];
            *(float4*)&a[4]  = *(const float4*)&QsT[dd * 132 + ty * 8 + 4];
            *(float4*)&bb[0] = *(const float4*)&KsT[dd * 132 + tx * 8];
            *(float4*)&bb[4] = *(const float4*)&KsT[dd * 132 + tx * 8 + 4];
#pragma unroll
            for (int i = 0; i < 8; i++)
#pragma unroll
                for (int j = 0; j < 8; j++)
                    acc[i][j] = fmaf(a[i], bb[j], acc[i][j]);
        }

        if (kt == qt) {  // causal mask on diagonal tile
#pragma unroll
            for (int i = 0; i < 8; i++) {
                int q = ty * 8 + i;
#pragma unroll
                for (int j = 0; j < 8; j++) {
                    int k = tx * 8 + j;
                    if (k > q) acc[i][j] = -1e9f;
                }
            }
        }

        // online softmax; row groups share ty -> reduce across 16 tx lanes
#pragma unroll
        for (int i = 0; i < 8; i++) {
            float mx = acc[i][0];
#pragma unroll
            for (int j = 1; j < 8; j++) mx = fmaxf(mx, acc[i][j]);
#pragma unroll
            for (int off = 8; off; off >>= 1)
                mx = fmaxf(mx, __shfl_xor_sync(0xffffffffu, mx, off));
            float mnew = fmaxf(mrow[i], mx);
            float corr = __expf(mrow[i] - mnew);  // -inf - finite -> 0 on 1st tile
            mrow[i] = mnew;
            float rs = 0.f;
#pragma unroll
            for (int j = 0; j < 8; j++) {
                float p = __expf(acc[i][j] - mnew);
                acc[i][j] = p;
                rs += p;
            }
#pragma unroll
            for (int off = 8; off; off >>= 1)
                rs += __shfl_xor_sync(0xffffffffu, rs, off);
            lrow[i] = lrow[i] * corr + rs;
#pragma unroll
            for (int j = 0; j < 4; j++) O[i][j] *= corr;
            *(float4*)&Ps[(ty * 8 + i) * 132 + tx * 8]     = *(float4*)&acc[i][0];
            *(float4*)&Ps[(ty * 8 + i) * 132 + tx * 8 + 4] = *(float4*)&acc[i][4];
        }
        __syncthreads();

        // O += P @ V   (vectorized over kk to keep smem port off the critical path)
#pragma unroll 2
        for (int kk = 0; kk < 128; kk += 4) {
            float a4[8][4];
#pragma unroll
            for (int i = 0; i < 8; i++)
                *(float4*)a4[i] = *(const float4*)&Ps[(ty * 8 + i) * 132 + kk];
#pragma unroll
            for (int u = 0; u < 4; u++) {
                float4 bv = *(const float4*)&Vs[(kk + u) * 68 + tx * 4];
#pragma unroll
                for (int i = 0; i < 8; i++) {
                    O[i][0] = fmaf(a4[i][u], bv.x, O[i][0]);
                    O[i][1] = fmaf(a4[i][u], bv.y, O[i][1]);
                    O[i][2] = fmaf(a4[i][u], bv.z, O[i][2]);
                    O[i][3] = fmaf(a4[i][u], bv.w, O[i][3]);
                }
            }
        }
    }

    // epilogue: Out[(b*S+q)*1024 + h*64 + d]
#pragma unroll
    for (int i = 0; i < 8; i++) {
        int q = qbase + ty * 8 + i;
        float inv = 1.f / lrow[i];
        float4 v;
        v.x = O[i][0] * inv; v.y = O[i][1] * inv;
        v.z = O[i][2] * inv; v.w = O[i][3] * inv;
        *(float4*)&Out[((size_t)(b * SEQ + q)) * DM + h * DH + tx * 4] = v;
    }
}

// ---------------------------------------------------------------------------
extern "C" void kernel_launch(void* const* d_in, const int* in_sizes, int n_in,
                              void* d_out, int out_size)
{
    (void)in_sizes; (void)n_in; (void)out_size;
    const float* q  = (const float*)d_in[0];
    const float* k  = (const float*)d_in[1];
    const float* v  = (const float*)d_in[2];
    const float* wq = (const float*)d_in[3];
    const float* bq = (const float*)d_in[4];
    const float* wk = (const float*)d_in[5];
    const float* bk = (const float*)d_in[6];
    const float* wv = (const float*)d_in[7];
    const float* bv = (const float*)d_in[8];
    const float* wo = (const float*)d_in[9];
    const float* bo = (const float*)d_in[10];
    float* out = (float*)d_out;

    float *qh, *kh, *vh, *att;
    cudaGetSymbolAddress((void**)&qh,  g_qh);
    cudaGetSymbolAddress((void**)&kh,  g_kh);
    cudaGetSymbolAddress((void**)&vh,  g_vh);
    cudaGetSymbolAddress((void**)&att, g_att);

    const int M = BATCH * SEQ;  // 4096
    dim3 gg(DM / 128, M / 128); // (8, 32)

    gemm_bias_k<1><<<gg, 256>>>(q, wq, bq, qh, M, DM, DM);
    gemm_bias_k<1><<<gg, 256>>>(k, wk, bk, kh, M, DM, DM);
    gemm_bias_k<1><<<gg, 256>>>(v, wv, bv, vh, M, DM, DM);

    static bool attr_set = false;
    cudaFuncSetAttribute(attn_k, cudaFuncAttributeMaxDynamicSharedMemorySize,
                         SM_BYTES);
    (void)attr_set;

    attn_k<<<dim3(SEQ / 128, NH, BATCH), 256, SM_BYTES>>>(qh, kh, vh, att);

    gemm_bias_k<0><<<gg, 256>>>(att, wo, bo, out, M, DM, DM);
}

// round 6
// speedup vs baseline: 1.4046x; 1.4046x over previous
#include <cuda_runtime.h>
#include <cuda_bf16.h>
#include <math.h>
#include <stdint.h>

#define BATCH 2
#define SEQ   2048
#define DM    1024
#define NH    16
#define DH    64

// ---------------- scratch (__device__ globals; no allocation allowed) -------
__device__ float g_qh[BATCH * NH * SEQ * DH];   // [b,h,s,d]
__device__ float g_kh[BATCH * NH * SEQ * DH];
__device__ float g_vh[BATCH * NH * SEQ * DH];
__device__ float g_att[BATCH * SEQ * DM];       // [b*s, h*64+d]

__device__ __nv_bfloat16 g_ahi[BATCH * SEQ * DM];   // A split hi  [M,K]
__device__ __nv_bfloat16 g_alo[BATCH * SEQ * DM];   // A split lo
__device__ __nv_bfloat16 g_whi[DM * DM];            // W^T split hi [N,K]
__device__ __nv_bfloat16 g_wlo[DM * DM];            // W^T split lo

// ---------------------------------------------------------------------------
// helpers (stable PTX only: sm_80-class instructions, valid on sm_103)
// ---------------------------------------------------------------------------
__device__ __forceinline__ uint32_t s2u(const void* p) {
    uint32_t a;
    asm("{ .reg .u64 t; cvta.to.shared.u64 t, %1; cvt.u32.u64 %0, t; }"
        : "=r"(a) : "l"(p));
    return a;
}

__device__ __forceinline__ void cp16(uint32_t saddr, const void* gptr) {
    asm volatile("cp.async.cg.shared.global [%0], [%1], 16;"
                 :: "r"(saddr), "l"(gptr) : "memory");
}

__device__ __forceinline__ void ldm_x4(uint32_t* r, uint32_t addr) {
    asm volatile("ldmatrix.sync.aligned.m8n8.x4.shared.b16 {%0,%1,%2,%3}, [%4];"
                 : "=r"(r[0]), "=r"(r[1]), "=r"(r[2]), "=r"(r[3]) : "r"(addr));
}

__device__ __forceinline__ void mma16816(float* c, const uint32_t* a,
                                         uint32_t b0, uint32_t b1) {
    asm volatile(
        "mma.sync.aligned.m16n8k16.row.col.f32.bf16.bf16.f32 "
        "{%0,%1,%2,%3}, {%4,%5,%6,%7}, {%8,%9}, {%0,%1,%2,%3};"
        : "+f"(c[0]), "+f"(c[1]), "+f"(c[2]), "+f"(c[3])
        : "r"(a[0]), "r"(a[1]), "r"(a[2]), "r"(a[3]), "r"(b0), "r"(b1));
}

// ---------------------------------------------------------------------------
// conversion kernels: fp32 -> (bf16 hi, bf16 lo)
// ---------------------------------------------------------------------------
__global__ __launch_bounds__(256) void convA(const float4* __restrict__ x,
                                             __nv_bfloat16* __restrict__ hi,
                                             __nv_bfloat16* __restrict__ lo, int n4)
{
    int i = blockIdx.x * 256 + threadIdx.x;
    if (i >= n4) return;
    float4 v = x[i];
    __nv_bfloat16 h0 = __float2bfloat16(v.x), h1 = __float2bfloat16(v.y);
    __nv_bfloat16 h2 = __float2bfloat16(v.z), h3 = __float2bfloat16(v.w);
    __nv_bfloat16 l0 = __float2bfloat16(v.x - __bfloat162float(h0));
    __nv_bfloat16 l1 = __float2bfloat16(v.y - __bfloat162float(h1));
    __nv_bfloat16 l2 = __float2bfloat16(v.z - __bfloat162float(h2));
    __nv_bfloat16 l3 = __float2bfloat16(v.w - __bfloat162float(h3));
    ((__nv_bfloat162*)hi)[2 * i]     = __halves2bfloat162(h0, h1);
    ((__nv_bfloat162*)hi)[2 * i + 1] = __halves2bfloat162(h2, h3);
    ((__nv_bfloat162*)lo)[2 * i]     = __halves2bfloat162(l0, l1);
    ((__nv_bfloat162*)lo)[2 * i + 1] = __halves2bfloat162(l2, l3);
}

// W[K,N] -> W^T hi/lo [N,K]
__global__ __launch_bounds__(256) void convW(const float* __restrict__ W,
                                             __nv_bfloat16* __restrict__ hiT,
                                             __nv_bfloat16* __restrict__ loT)
{
    __shared__ float t[32][33];
    int n0 = blockIdx.x * 32, k0 = blockIdx.y * 32;
    int tx = threadIdx.x & 31, ty = threadIdx.x >> 5;  // (32, 8)
#pragma unroll
    for (int j = 0; j < 32; j += 8)
        t[ty + j][tx] = W[(size_t)(k0 + ty + j) * DM + n0 + tx];
    __syncthreads();
#pragma unroll
    for (int j = 0; j < 32; j += 8) {
        float x = t[tx][ty + j];
        __nv_bfloat16 h = __float2bfloat16(x);
        hiT[(size_t)(n0 + ty + j) * DM + k0 + tx] = h;
        loT[(size_t)(n0 + ty + j) * DM + k0 + tx] =
            __float2bfloat16(x - __bfloat162float(h));
    }
}

// ---------------------------------------------------------------------------
// split-bf16 GEMM on mma.sync: C[M,N] = A[M,K] @ W[K,N] + bias
// CTA tile 128x128, K-tile 64, 2-stage cp.async pipeline, 8 warps (2m x 4n),
// warp tile 64x32, m16n8k16, 3 split passes (hh, hl, lh).
// ---------------------------------------------------------------------------
#define GP     72                      // padded row pitch in bf16 (144 B)
#define ARR_B  (128 * GP * 2)          // 18432 B, one 128x64 tile
#define STG_B  (4 * ARR_B)             // Ah, Al, Bh, Bl
#define GSMEM_B (2 * STG_B)            // 147456 B

template <int MODE>
__global__ __launch_bounds__(256, 1) void gemm_mma(
    const __nv_bfloat16* __restrict__ Ah, const __nv_bfloat16* __restrict__ Al,
    const __nv_bfloat16* __restrict__ Bh, const __nv_bfloat16* __restrict__ Bl,
    const float* __restrict__ bias, float* __restrict__ C)
{
    extern __shared__ __align__(128) char dynsmem[];
    const uint32_t smb = s2u(dynsmem);
    const int tid  = threadIdx.x;
    const int lane = tid & 31;
    const int wid  = tid >> 5;
    const int warp_m = wid >> 2;        // 0..1
    const int warp_n = wid & 3;         // 0..3
    const int mbase = blockIdx.y * 128;
    const int nbase = blockIdx.x * 128;

    const int lrow = tid >> 3;          // 0..31
    const int lcol = (tid & 7) * 8;     // bf16 col within 64

    float c[4][4][4];
#pragma unroll
    for (int i = 0; i < 4; i++)
#pragma unroll
        for (int j = 0; j < 4; j++)
#pragma unroll
            for (int r = 0; r < 4; r++) c[i][j][r] = 0.f;

    // prologue: k-tile 0 -> stage 0
    {
        const int kc = lcol;
        const uint32_t sb = smb;
#pragma unroll
        for (int p = 0; p < 4; ++p) {
            const int r = p * 32 + lrow;
            const uint32_t so = (uint32_t)(r * GP + lcol) * 2;
            cp16(sb + so,             &Ah[(size_t)(mbase + r) * DM + kc]);
            cp16(sb + ARR_B + so,     &Al[(size_t)(mbase + r) * DM + kc]);
            cp16(sb + 2 * ARR_B + so, &Bh[(size_t)(nbase + r) * DM + kc]);
            cp16(sb + 3 * ARR_B + so, &Bl[(size_t)(nbase + r) * DM + kc]);
        }
        asm volatile("cp.async.commit_group;" ::: "memory");
    }

    for (int kt = 0; kt < 16; ++kt) {
        const int s = kt & 1;
        asm volatile("cp.async.wait_group 0;" ::: "memory");
        __syncthreads();
        if (kt < 15) {
            const int kc = (kt + 1) * 64 + lcol;
            const uint32_t sb2 = smb + (s ^ 1) * STG_B;
#pragma unroll
            for (int p = 0; p < 4; ++p) {
                const int r = p * 32 + lrow;
                const uint32_t so = (uint32_t)(r * GP + lcol) * 2;
                cp16(sb2 + so,             &Ah[(size_t)(mbase + r) * DM + kc]);
                cp16(sb2 + ARR_B + so,     &Al[(size_t)(mbase + r) * DM + kc]);
                cp16(sb2 + 2 * ARR_B + so, &Bh[(size_t)(nbase + r) * DM + kc]);
                cp16(sb2 + 3 * ARR_B + so, &Bl[(size_t)(nbase + r) * DM + kc]);
            }
            asm volatile("cp.async.commit_group;" ::: "memory");
        }

        const uint32_t sb = smb + s * STG_B;
#pragma unroll
        for (int ks = 0; ks < 4; ++ks) {
            const uint32_t lm_off =
                (uint32_t)((lane & 15) * GP + ks * 16 + (lane >> 4) * 8) * 2;

            uint32_t ah[4][4], al[4][4];
#pragma unroll
            for (int am = 0; am < 4; ++am) {
                const uint32_t ro = (uint32_t)((warp_m * 64 + am * 16) * GP) * 2;
                ldm_x4(ah[am], sb + ro + lm_off);
                ldm_x4(al[am], sb + ARR_B + ro + lm_off);
            }
            uint32_t bh[2][4], bl[2][4];
#pragma unroll
            for (int g = 0; g < 2; ++g) {
                const uint32_t ro = (uint32_t)((warp_n * 32 + g * 16) * GP) * 2;
                ldm_x4(bh[g], sb + 2 * ARR_B + ro + lm_off);
                ldm_x4(bl[g], sb + 3 * ARR_B + ro + lm_off);
            }
#pragma unroll
            for (int am = 0; am < 4; ++am) {
#pragma unroll
                for (int bn = 0; bn < 4; ++bn) {
                    const int g = bn >> 1, hf = bn & 1;
                    mma16816(c[am][bn], ah[am], bh[g][hf], bh[g][hf + 2]); // hi*hi
                    mma16816(c[am][bn], ah[am], bl[g][hf], bl[g][hf + 2]); // hi*lo
                    mma16816(c[am][bn], al[am], bh[g][hf], bh[g][hf + 2]); // lo*hi
                }
            }
        }
    }

    // epilogue: frag lane l holds C[r + {0,8}][2(l%4) + {0,1}]
#pragma unroll
    for (int am = 0; am < 4; ++am) {
        const int row0 = mbase + warp_m * 64 + am * 16 + (lane >> 2);
#pragma unroll
        for (int bn = 0; bn < 4; ++bn) {
            const int col = nbase + warp_n * 32 + bn * 8 + 2 * (lane & 3);
            const float b0 = bias[col], b1 = bias[col + 1];
            float2 v0 = make_float2(c[am][bn][0] + b0, c[am][bn][1] + b1);
            float2 v1 = make_float2(c[am][bn][2] + b0, c[am][bn][3] + b1);
            if (MODE == 0) {
                *(float2*)&C[(size_t)row0 * DM + col]       = v0;
                *(float2*)&C[(size_t)(row0 + 8) * DM + col] = v1;
            } else {
                const int h_ = col >> 6, d_ = col & 63;
                int b_ = row0 >> 11, s_ = row0 & 2047;
                *(float2*)&C[(((size_t)(b_ * NH + h_)) * SEQ + s_) * DH + d_] = v0;
                const int r1 = row0 + 8;
                b_ = r1 >> 11; s_ = r1 & 2047;
                *(float2*)&C[(((size_t)(b_ * NH + h_)) * SEQ + s_) * DH + d_] = v1;
            }
        }
    }
}

// ---------------------------------------------------------------------------
// Flash attention, fp32, causal, UNSCALED scores (unchanged, proven in R1)
// ---------------------------------------------------------------------------
#define ATT_SM_FLOATS (2 * 64 * 132 + 128 * 68 + 128 * 132)
#define ATT_SM_BYTES  (ATT_SM_FLOATS * 4)

__global__ __launch_bounds__(256, 1) void attn_k(
    const float* __restrict__ Qh, const float* __restrict__ Kh,
    const float* __restrict__ Vh, float* __restrict__ Out)
{
    extern __shared__ __align__(128) char dynsmem[];
    float* smf = (float*)dynsmem;
    float* QsT = smf;
    float* KsT = smf + 64 * 132;
    float* Vs  = smf + 2 * 64 * 132;
    float* Ps  = smf + 2 * 64 * 132 + 128 * 68;

    const int tid = threadIdx.x;
    const int tx = tid & 15, ty = tid >> 4;
    const int qt = blockIdx.x;
    const int h  = blockIdx.y;
    const int b  = blockIdx.z;
    const size_t base = ((size_t)(b * NH + h)) * SEQ * DH;
    const int qbase = qt * 128;

#pragma unroll
    for (int p = 0; p < 8; p++) {
        int f = p * 256 + tid;
        int r = f & 127, c4 = f >> 7;
        float4 v = *(const float4*)&Qh[base + (size_t)(qbase + r) * DH + c4 * 4];
        QsT[(c4 * 4 + 0) * 132 + r] = v.x;
        QsT[(c4 * 4 + 1) * 132 + r] = v.y;
        QsT[(c4 * 4 + 2) * 132 + r] = v.z;
        QsT[(c4 * 4 + 3) * 132 + r] = v.w;
    }

    float O[8][4];
    float mrow[8], lrow[8];
#pragma unroll
    for (int i = 0; i < 8; i++) {
        mrow[i] = -INFINITY; lrow[i] = 0.f;
#pragma unroll
        for (int j = 0; j < 4; j++) O[i][j] = 0.f;
    }

    for (int kt = 0; kt <= qt; kt++) {
        const int kbase = kt * 128;
        __syncthreads();
#pragma unroll
        for (int p = 0; p < 8; p++) {
            int f = p * 256 + tid;
            int r = f & 127, c4 = f >> 7;
            float4 v = *(const float4*)&Kh[base + (size_t)(kbase + r) * DH + c4 * 4];
            KsT[(c4 * 4 + 0) * 132 + r] = v.x;
            KsT[(c4 * 4 + 1) * 132 + r] = v.y;
            KsT[(c4 * 4 + 2) * 132 + r] = v.z;
            KsT[(c4 * 4 + 3) * 132 + r] = v.w;
        }
#pragma unroll
        for (int p = 0; p < 8; p++) {
            int f = p * 256 + tid;
            int r = f >> 4, c4 = f & 15;
            *(float4*)&Vs[r * 68 + c4 * 4] =
                *(const float4*)&Vh[base + (size_t)(kbase + r) * DH + c4 * 4];
        }
        __syncthreads();

        float acc[8][8];
#pragma unroll
        for (int i = 0; i < 8; i++)
#pragma unroll
            for (int j = 0; j < 8; j++) acc[i][j] = 0.f;

#pragma unroll 4
        for (int dd = 0; dd < 64; dd++) {
            float a[8], bb[8];
            *(float4*)&a[0]  = *(const float4*)&QsT[dd * 132 + ty * 8];
            *(float4*)&a[4]  = *(const float4*)&QsT[dd * 132 + ty * 8 + 4];
            *(float4*)&bb[0] = *(const float4*)&KsT[dd * 132 + tx * 8];
            *(float4*)&bb[4] = *(const float4*)&KsT[dd * 132 + tx * 8 + 4];
#pragma unroll
            for (int i = 0; i < 8; i++)
#pragma unroll
                for (int j = 0; j < 8; j++)
                    acc[i][j] = fmaf(a[i], bb[j], acc[i][j]);
        }

        if (kt == qt) {
#pragma unroll
            for (int i = 0; i < 8; i++) {
                int q = ty * 8 + i;
#pragma unroll
                for (int j = 0; j < 8; j++) {
                    int k = tx * 8 + j;
                    if (k > q) acc[i][j] = -1e9f;
                }
            }
        }

#pragma unroll
        for (int i = 0; i < 8; i++) {
            float mx = acc[i][0];
#pragma unroll
            for (int j = 1; j < 8; j++) mx = fmaxf(mx, acc[i][j]);
#pragma unroll
            for (int off = 8; off; off >>= 1)
                mx = fmaxf(mx, __shfl_xor_sync(0xffffffffu, mx, off));
            float mnew = fmaxf(mrow[i], mx);
            float corr = __expf(mrow[i] - mnew);
            mrow[i] = mnew;
            float rs = 0.f;
#pragma unroll
            for (int j = 0; j < 8; j++) {
                float p = __expf(acc[i][j] - mnew);
                acc[i][j] = p;
                rs += p;
            }
#pragma unroll
            for (int off = 8; off; off >>= 1)
                rs += __shfl_xor_sync(0xffffffffu, rs, off);
            lrow[i] = lrow[i] * corr + rs;
#pragma unroll
            for (int j = 0; j < 4; j++) O[i][j] *= corr;
            *(float4*)&Ps[(ty * 8 + i) * 132 + tx * 8]     = *(float4*)&acc[i][0];
            *(float4*)&Ps[(ty * 8 + i) * 132 + tx * 8 + 4] = *(float4*)&acc[i][4];
        }
        __syncthreads();

#pragma unroll 2
        for (int kk = 0; kk < 128; kk += 4) {
            float a4[8][4];
#pragma unroll
            for (int i = 0; i < 8; i++)
                *(float4*)a4[i] = *(const float4*)&Ps[(ty * 8 + i) * 132 + kk];
#pragma unroll
            for (int u = 0; u < 4; u++) {
                float4 bv = *(const float4*)&Vs[(kk + u) * 68 + tx * 4];
#pragma unroll
                for (int i = 0; i < 8; i++) {
                    O[i][0] = fmaf(a4[i][u], bv.x, O[i][0]);
                    O[i][1] = fmaf(a4[i][u], bv.y, O[i][1]);
                    O[i][2] = fmaf(a4[i][u], bv.z, O[i][2]);
                    O[i][3] = fmaf(a4[i][u], bv.w, O[i][3]);
                }
            }
        }
    }

#pragma unroll
    for (int i = 0; i < 8; i++) {
        int q = qbase + ty * 8 + i;
        float inv = 1.f / lrow[i];
        float4 v;
        v.x = O[i][0] * inv; v.y = O[i][1] * inv;
        v.z = O[i][2] * inv; v.w = O[i][3] * inv;
        *(float4*)&Out[((size_t)(b * SEQ + q)) * DM + h * DH + tx * 4] = v;
    }
}

// ---------------------------------------------------------------------------
extern "C" void kernel_launch(void* const* d_in, const int* in_sizes, int n_in,
                              void* d_out, int out_size)
{
    (void)in_sizes; (void)n_in; (void)out_size;
    const float* q  = (const float*)d_in[0];
    const float* k  = (const float*)d_in[1];
    const float* v  = (const float*)d_in[2];
    const float* wq = (const float*)d_in[3];
    const float* bq = (const float*)d_in[4];
    const float* wk = (const float*)d_in[5];
    const float* bk = (const float*)d_in[6];
    const float* wv = (const float*)d_in[7];
    const float* bv = (const float*)d_in[8];
    const float* wo = (const float*)d_in[9];
    const float* bo = (const float*)d_in[10];
    float* out = (float*)d_out;

    float *qh, *kh, *vh, *att;
    __nv_bfloat16 *ahi, *alo, *whi, *wlo;
    cudaGetSymbolAddress((void**)&qh,  g_qh);
    cudaGetSymbolAddress((void**)&kh,  g_kh);
    cudaGetSymbolAddress((void**)&vh,  g_vh);
    cudaGetSymbolAddress((void**)&att, g_att);
    cudaGetSymbolAddress((void**)&ahi, g_ahi);
    cudaGetSymbolAddress((void**)&alo, g_alo);
    cudaGetSymbolAddress((void**)&whi, g_whi);
    cudaGetSymbolAddress((void**)&wlo, g_wlo);

    cudaFuncSetAttribute(gemm_mma<0>, cudaFuncAttributeMaxDynamicSharedMemorySize, GSMEM_B);
    cudaFuncSetAttribute(gemm_mma<1>, cudaFuncAttributeMaxDynamicSharedMemorySize, GSMEM_B);
    cudaFuncSetAttribute(attn_k,      cudaFuncAttributeMaxDynamicSharedMemorySize, ATT_SM_BYTES);

    const int M = BATCH * SEQ;                  // 4096
    const int n4A = M * DM / 4;                 // 1048576
    dim3 cg(n4A / 256);                         // convA grid
    dim3 wg(DM / 32, DM / 32);                  // convW grid
    dim3 gg(DM / 128, M / 128);                 // gemm grid (8, 32)

    // Q projection
    convW<<<wg, 256>>>(wq, whi, wlo);
    convA<<<cg, 256>>>((const float4*)q, ahi, alo, n4A);
    gemm_mma<1><<<gg, 256, GSMEM_B>>>(ahi, alo, whi, wlo, bq, qh);
    // K projection
    convW<<<wg, 256>>>(wk, whi, wlo);
    convA<<<cg, 256>>>((const float4*)k, ahi, alo, n4A);
    gemm_mma<1><<<gg, 256, GSMEM_B>>>(ahi, alo, whi, wlo, bk, kh);
    // V projection
    convW<<<wg, 256>>>(wv, whi, wlo);
    convA<<<cg, 256>>>((const float4*)v, ahi, alo, n4A);
    gemm_mma<1><<<gg, 256, GSMEM_B>>>(ahi, alo, whi, wlo, bv, vh);

    // attention (fp32 flash)
    attn_k<<<dim3(SEQ / 128, NH, BATCH), 256, ATT_SM_BYTES>>>(qh, kh, vh, att);

    // output projection
    convW<<<wg, 256>>>(wo, whi, wlo);
    convA<<<cg, 256>>>((const float4*)att, ahi, alo, n4A);
    gemm_mma<0><<<gg, 256, GSMEM_B>>>(ahi, alo, whi, wlo, bo, out);
}

// round 8
// speedup vs baseline: 2.2114x; 1.5744x over previous
#include <cuda_runtime.h>
#include <cuda_bf16.h>
#include <math.h>
#include <stdint.h>

#define BATCH 2
#define SEQ   2048
#define DM    1024
#define NH    16
#define DH    64

// ---------------- scratch (__device__ globals; no allocation allowed) -------
__device__ __nv_bfloat16 g_qhi[BATCH * NH * SEQ * DH];  // [b,h,s,d]
__device__ __nv_bfloat16 g_qlo[BATCH * NH * SEQ * DH];
__device__ __nv_bfloat16 g_khi[BATCH * NH * SEQ * DH];
__device__ __nv_bfloat16 g_klo[BATCH * NH * SEQ * DH];
__device__ __nv_bfloat16 g_vthi[BATCH * NH * DH * SEQ]; // [b,h,d,s] (transposed)
__device__ __nv_bfloat16 g_vtlo[BATCH * NH * DH * SEQ];
__device__ __nv_bfloat16 g_ahi[BATCH * SEQ * DM];       // GEMM A hi [M,K]
__device__ __nv_bfloat16 g_alo[BATCH * SEQ * DM];
__device__ __nv_bfloat16 g_whi[DM * DM];                // W^T hi [N,K]
__device__ __nv_bfloat16 g_wlo[DM * DM];

// ---------------------------------------------------------------------------
// helpers (stable PTX only; valid on plain sm_103)
// ---------------------------------------------------------------------------
__device__ __forceinline__ uint32_t s2u(const void* p) {
    uint32_t a;
    asm("{ .reg .u64 t; cvta.to.shared.u64 t, %1; cvt.u32.u64 %0, t; }"
        : "=r"(a) : "l"(p));
    return a;
}
__device__ __forceinline__ void cp16(uint32_t saddr, const void* gptr) {
    asm volatile("cp.async.cg.shared.global [%0], [%1], 16;"
                 :: "r"(saddr), "l"(gptr) : "memory");
}
__device__ __forceinline__ void ldm_x4(uint32_t* r, uint32_t addr) {
    asm volatile("ldmatrix.sync.aligned.m8n8.x4.shared.b16 {%0,%1,%2,%3}, [%4];"
                 : "=r"(r[0]), "=r"(r[1]), "=r"(r[2]), "=r"(r[3]) : "r"(addr));
}
__device__ __forceinline__ void mma16816(float* c, const uint32_t* a,
                                         uint32_t b0, uint32_t b1) {
    asm volatile(
        "mma.sync.aligned.m16n8k16.row.col.f32.bf16.bf16.f32 "
        "{%0,%1,%2,%3}, {%4,%5,%6,%7}, {%8,%9}, {%0,%1,%2,%3};"
        : "+f"(c[0]), "+f"(c[1]), "+f"(c[2]), "+f"(c[3])
        : "r"(a[0]), "r"(a[1]), "r"(a[2]), "r"(a[3]), "r"(b0), "r"(b1));
}
// pack two f32 -> bf16x2 (first arg in low half)
__device__ __forceinline__ uint32_t packbf2(float lo, float hi) {
    uint32_t r;
    asm("cvt.rn.bf16x2.f32 %0, %1, %2;" : "=r"(r) : "f"(hi), "f"(lo));
    return r;
}
__device__ __forceinline__ float lowf(uint32_t u)  { return __uint_as_float(u << 16); }
__device__ __forceinline__ float highf(uint32_t u) { return __uint_as_float(u & 0xFFFF0000u); }

// ---------------------------------------------------------------------------
// conversion kernels: fp32 -> (bf16 hi, bf16 lo)
// ---------------------------------------------------------------------------
__global__ __launch_bounds__(256) void convA(const float4* __restrict__ x,
                                             __nv_bfloat16* __restrict__ hi,
                                             __nv_bfloat16* __restrict__ lo, int n4)
{
    int i = blockIdx.x * 256 + threadIdx.x;
    if (i >= n4) return;
    float4 v = x[i];
    uint32_t h0 = packbf2(v.x, v.y), h1 = packbf2(v.z, v.w);
    uint32_t l0 = packbf2(v.x - lowf(h0), v.y - highf(h0));
    uint32_t l1 = packbf2(v.z - lowf(h1), v.w - highf(h1));
    ((uint32_t*)hi)[2 * i]     = h0;
    ((uint32_t*)hi)[2 * i + 1] = h1;
    ((uint32_t*)lo)[2 * i]     = l0;
    ((uint32_t*)lo)[2 * i + 1] = l1;
}

// W[K,N] -> W^T hi/lo [N,K]
__global__ __launch_bounds__(256) void convW(const float* __restrict__ W,
                                             __nv_bfloat16* __restrict__ hiT,
                                             __nv_bfloat16* __restrict__ loT)
{
    __shared__ float t[32][33];
    int n0 = blockIdx.x * 32, k0 = blockIdx.y * 32;
    int tx = threadIdx.x & 31, ty = threadIdx.x >> 5;
#pragma unroll
    for (int j = 0; j < 32; j += 8)
        t[ty + j][tx] = W[(size_t)(k0 + ty + j) * DM + n0 + tx];
    __syncthreads();
#pragma unroll
    for (int j = 0; j < 32; j += 8) {
        float x = t[tx][ty + j];
        __nv_bfloat16 h = __float2bfloat16(x);
        hiT[(size_t)(n0 + ty + j) * DM + k0 + tx] = h;
        loT[(size_t)(n0 + ty + j) * DM + k0 + tx] =
            __float2bfloat16(x - __bfloat162float(h));
    }
}

// ---------------------------------------------------------------------------
// split-bf16 GEMM on mma.sync (structure proven in R6).
// MODE 0: fp32 row-major out.  MODE 1: bf16 hi/lo [b,h,s,d].
// MODE 2: bf16 hi/lo transposed [b,h,d,s] (for V).
// ---------------------------------------------------------------------------
#define GP     72
#define ARR_B  (128 * GP * 2)
#define STG_B  (4 * ARR_B)
#define GSMEM_B (2 * STG_B)

template <int MODE>
__global__ __launch_bounds__(256, 1) void gemm_mma(
    const __nv_bfloat16* __restrict__ Ah, const __nv_bfloat16* __restrict__ Al,
    const __nv_bfloat16* __restrict__ Bh, const __nv_bfloat16* __restrict__ Bl,
    const float* __restrict__ bias, float* __restrict__ Cf,
    __nv_bfloat16* __restrict__ Chi, __nv_bfloat16* __restrict__ Clo)
{
    extern __shared__ __align__(128) char dynsmem[];
    const uint32_t smb = s2u(dynsmem);
    const int tid  = threadIdx.x;
    const int lane = tid & 31;
    const int wid  = tid >> 5;
    const int warp_m = wid >> 2;
    const int warp_n = wid & 3;
    const int mbase = blockIdx.y * 128;
    const int nbase = blockIdx.x * 128;

    const int lrow = tid >> 3;
    const int lcol = (tid & 7) * 8;

    float c[4][4][4];
#pragma unroll
    for (int i = 0; i < 4; i++)
#pragma unroll
        for (int j = 0; j < 4; j++)
#pragma unroll
            for (int r = 0; r < 4; r++) c[i][j][r] = 0.f;

    {
        const int kc = lcol;
#pragma unroll
        for (int p = 0; p < 4; ++p) {
            const int r = p * 32 + lrow;
            const uint32_t so = (uint32_t)(r * GP + lcol) * 2;
            cp16(smb + so,             &Ah[(size_t)(mbase + r) * DM + kc]);
            cp16(smb + ARR_B + so,     &Al[(size_t)(mbase + r) * DM + kc]);
            cp16(smb + 2 * ARR_B + so, &Bh[(size_t)(nbase + r) * DM + kc]);
            cp16(smb + 3 * ARR_B + so, &Bl[(size_t)(nbase + r) * DM + kc]);
        }
        asm volatile("cp.async.commit_group;" ::: "memory");
    }

    for (int kt = 0; kt < 16; ++kt) {
        const int s = kt & 1;
        asm volatile("cp.async.wait_group 0;" ::: "memory");
        __syncthreads();
        if (kt < 15) {
            const int kc = (kt + 1) * 64 + lcol;
            const uint32_t sb2 = smb + (s ^ 1) * STG_B;
#pragma unroll
            for (int p = 0; p < 4; ++p) {
                const int r = p * 32 + lrow;
                const uint32_t so = (uint32_t)(r * GP + lcol) * 2;
                cp16(sb2 + so,             &Ah[(size_t)(mbase + r) * DM + kc]);
                cp16(sb2 + ARR_B + so,     &Al[(size_t)(mbase + r) * DM + kc]);
                cp16(sb2 + 2 * ARR_B + so, &Bh[(size_t)(nbase + r) * DM + kc]);
                cp16(sb2 + 3 * ARR_B + so, &Bl[(size_t)(nbase + r) * DM + kc]);
            }
            asm volatile("cp.async.commit_group;" ::: "memory");
        }

        const uint32_t sb = smb + s * STG_B;
#pragma unroll
        for (int ks = 0; ks < 4; ++ks) {
            const uint32_t lm_off =
                (uint32_t)((lane & 15) * GP + ks * 16 + (lane >> 4) * 8) * 2;
            uint32_t ah[4][4], al[4][4];
#pragma unroll
            for (int am = 0; am < 4; ++am) {
                const uint32_t ro = (uint32_t)((warp_m * 64 + am * 16) * GP) * 2;
                ldm_x4(ah[am], sb + ro + lm_off);
                ldm_x4(al[am], sb + ARR_B + ro + lm_off);
            }
            uint32_t bh[2][4], bl[2][4];
#pragma unroll
            for (int g = 0; g < 2; ++g) {
                const uint32_t ro = (uint32_t)((warp_n * 32 + g * 16) * GP) * 2;
                ldm_x4(bh[g], sb + 2 * ARR_B + ro + lm_off);
                ldm_x4(bl[g], sb + 3 * ARR_B + ro + lm_off);
            }
#pragma unroll
            for (int am = 0; am < 4; ++am) {
#pragma unroll
                for (int bn = 0; bn < 4; ++bn) {
                    const int g = bn >> 1, hf = bn & 1;
                    mma16816(c[am][bn], ah[am], bh[g][hf], bh[g][hf + 2]);
                    mma16816(c[am][bn], ah[am], bl[g][hf], bl[g][hf + 2]);
                    mma16816(c[am][bn], al[am], bh[g][hf], bh[g][hf + 2]);
                }
            }
        }
    }

#pragma unroll
    for (int am = 0; am < 4; ++am) {
        const int row0 = mbase + warp_m * 64 + am * 16 + (lane >> 2);
#pragma unroll
        for (int bn = 0; bn < 4; ++bn) {
            const int col = nbase + warp_n * 32 + bn * 8 + 2 * (lane & 3);
            const float b0 = bias[col], b1 = bias[col + 1];
            float v00 = c[am][bn][0] + b0, v01 = c[am][bn][1] + b1;
            float v10 = c[am][bn][2] + b0, v11 = c[am][bn][3] + b1;
            if (MODE == 0) {
                *(float2*)&Cf[(size_t)row0 * DM + col]       = make_float2(v00, v01);
                *(float2*)&Cf[(size_t)(row0 + 8) * DM + col] = make_float2(v10, v11);
            } else if (MODE == 1) {
                const int h_ = col >> 6, d_ = col & 63;
                uint32_t h2 = packbf2(v00, v01);
                uint32_t l2 = packbf2(v00 - lowf(h2), v01 - highf(h2));
                int b_ = row0 >> 11, s_ = row0 & 2047;
                size_t i0 = (((size_t)(b_ * NH + h_)) * SEQ + s_) * DH + d_;
                *(uint32_t*)&Chi[i0] = h2; *(uint32_t*)&Clo[i0] = l2;
                h2 = packbf2(v10, v11);
                l2 = packbf2(v10 - lowf(h2), v11 - highf(h2));
                const int r1 = row0 + 8;
                b_ = r1 >> 11; s_ = r1 & 2047;
                i0 = (((size_t)(b_ * NH + h_)) * SEQ + s_) * DH + d_;
                *(uint32_t*)&Chi[i0] = h2; *(uint32_t*)&Clo[i0] = l2;
            } else {
                const int h_ = col >> 6, d_ = col & 63;
                int b_ = row0 >> 11, s_ = row0 & 2047;
                size_t bb = ((size_t)(b_ * NH + h_)) * DH;
#pragma unroll
                for (int e = 0; e < 4; ++e) {
                    float v = (e == 0) ? v00 : (e == 1) ? v01 : (e == 2) ? v10 : v11;
                    int dd = d_ + (e & 1);
                    int ss = s_ + ((e >> 1) * 8);
                    __nv_bfloat16 hh = __float2bfloat16(v);
                    Chi[(bb + dd) * SEQ + ss] = hh;
                    Clo[(bb + dd) * SEQ + ss] =
                        __float2bfloat16(v - __bfloat162float(hh));
                }
            }
        }
    }
}

// ---------------------------------------------------------------------------
// Flash attention on mma.sync, split-bf16 both GEMMs, causal, UNSCALED.
// 8 warps x 16 q-rows. Q regs persistent; S->P in-register; V pre-transposed.
// Writes O as bf16 hi/lo directly into the output-GEMM A buffers.
// ---------------------------------------------------------------------------
#define QP 72            // Q/K smem pitch (bf16)
#define VP 136           // Vt smem pitch (bf16)
#define AQ_B   (128 * QP * 2)          // 18432
#define AVT_B  (64 * VP * 2)           // 17408
#define ASTG_B (2 * AQ_B + 2 * AVT_B)  // 71680 per stage (Khi,Klo,Vthi,Vtlo)
#define ASM_B  (2 * AQ_B + 2 * ASTG_B) // 180224 total

__global__ __launch_bounds__(256, 1) void attn_mma(
    const __nv_bfloat16* __restrict__ Qhi, const __nv_bfloat16* __restrict__ Qlo,
    const __nv_bfloat16* __restrict__ Khi, const __nv_bfloat16* __restrict__ Klo,
    const __nv_bfloat16* __restrict__ Vthi, const __nv_bfloat16* __restrict__ Vtlo,
    __nv_bfloat16* __restrict__ Ahi, __nv_bfloat16* __restrict__ Alo)
{
    extern __shared__ __align__(128) char dynsmem[];
    const uint32_t smb = s2u(dynsmem);
    const int tid  = threadIdx.x;
    const int lane = tid & 31;
    const int wid  = tid >> 5;
    const int qt = blockIdx.x, h = blockIdx.y, b = blockIdx.z;
    const size_t base  = ((size_t)(b * NH + h)) * SEQ * DH;  // [s][d]
    const size_t vbase = ((size_t)(b * NH + h)) * DH * SEQ;  // [d][s]
    const int qbase = qt * 128;

    // ---- prologue: Q + stage 0 (K,Vt for kt=0) ----
#pragma unroll
    for (int p = 0; p < 4; ++p) {
        int idx = p * 256 + tid;
        int r = idx >> 3, cc = idx & 7;
        uint32_t so = (uint32_t)(r * QP + cc * 8) * 2;
        size_t g = base + (size_t)(qbase + r) * DH + cc * 8;
        cp16(smb + so, &Qhi[g]);
        cp16(smb + AQ_B + so, &Qlo[g]);
    }
    {
        const uint32_t stg = smb + 2 * AQ_B;
#pragma unroll
        for (int p = 0; p < 4; ++p) {
            int idx = p * 256 + tid;
            int r = idx >> 3, cc = idx & 7;
            uint32_t so = (uint32_t)(r * QP + cc * 8) * 2;
            size_t g = base + (size_t)r * DH + cc * 8;
            cp16(stg + so, &Khi[g]);
            cp16(stg + AQ_B + so, &Klo[g]);
        }
#pragma unroll
        for (int p = 0; p < 4; ++p) {
            int idx = p * 256 + tid;
            int r = idx >> 4, cc = idx & 15;
            uint32_t so = (uint32_t)(r * VP + cc * 8) * 2;
            size_t g = vbase + (size_t)r * SEQ + cc * 8;
            cp16(stg + 2 * AQ_B + so, &Vthi[g]);
            cp16(stg + 2 * AQ_B + AVT_B + so, &Vtlo[g]);
        }
    }
    asm volatile("cp.async.commit_group;" ::: "memory");
    asm volatile("cp.async.wait_group 0;" ::: "memory");
    __syncthreads();

    // ---- persistent Q fragments ----
    uint32_t qfh[4][4], qfl[4][4];
#pragma unroll
    for (int ks = 0; ks < 4; ++ks) {
        uint32_t a = smb + (uint32_t)((wid * 16 + (lane & 15)) * QP
                                      + ks * 16 + (lane >> 4) * 8) * 2;
        ldm_x4(qfh[ks], a);
        ldm_x4(qfl[ks], a + AQ_B);
    }

    float mr[2] = {-INFINITY, -INFINITY}, lr[2] = {0.f, 0.f};
    float o[8][4];
#pragma unroll
    for (int i = 0; i < 8; i++)
#pragma unroll
        for (int j = 0; j < 4; j++) o[i][j] = 0.f;

    for (int kt = 0; kt <= qt; ++kt) {
        const int s = kt & 1;
        if (kt > 0) {
            asm volatile("cp.async.wait_group 0;" ::: "memory");
            __syncthreads();
        }
        if (kt < qt) {  // prefetch next stage
            const int kb2 = (kt + 1) * 128;
            const uint32_t stg = smb + 2 * AQ_B + (s ^ 1) * ASTG_B;
#pragma unroll
            for (int p = 0; p < 4; ++p) {
                int idx = p * 256 + tid;
                int r = idx >> 3, cc = idx & 7;
                uint32_t so = (uint32_t)(r * QP + cc * 8) * 2;
                size_t g = base + (size_t)(kb2 + r) * DH + cc * 8;
                cp16(stg + so, &Khi[g]);
                cp16(stg + AQ_B + so, &Klo[g]);
            }
#pragma unroll
            for (int p = 0; p < 4; ++p) {
                int idx = p * 256 + tid;
                int r = idx >> 4, cc = idx & 15;
                uint32_t so = (uint32_t)(r * VP + cc * 8) * 2;
                size_t g = vbase + (size_t)r * SEQ + kb2 + cc * 8;
                cp16(stg + 2 * AQ_B + so, &Vthi[g]);
                cp16(stg + 2 * AQ_B + AVT_B + so, &Vtlo[g]);
            }
            asm volatile("cp.async.commit_group;" ::: "memory");
        }

        const uint32_t stg = smb + 2 * AQ_B + s * ASTG_B;

        // ---- S = Q @ K^T (3-pass split) ----
        float sc[16][4];
#pragma unroll
        for (int i = 0; i < 16; i++)
#pragma unroll
            for (int j = 0; j < 4; j++) sc[i][j] = 0.f;

#pragma unroll
        for (int ks = 0; ks < 4; ++ks) {
            const uint32_t lm = (uint32_t)((lane & 15) * QP + ks * 16
                                           + (lane >> 4) * 8) * 2;
#pragma unroll
            for (int g = 0; g < 8; ++g) {
                uint32_t kb[4], kl[4];
                uint32_t ro = (uint32_t)(g * 16 * QP) * 2;
                ldm_x4(kb, stg + ro + lm);
                ldm_x4(kl, stg + AQ_B + ro + lm);
#pragma unroll
                for (int hf = 0; hf < 2; ++hf) {
                    const int oct = g * 2 + hf;
                    mma16816(sc[oct], qfh[ks], kb[hf], kb[hf + 2]);
                    mma16816(sc[oct], qfh[ks], kl[hf], kl[hf + 2]);
                    mma16816(sc[oct], qfl[ks], kb[hf], kb[hf + 2]);
                }
            }
        }

        // ---- causal mask (diagonal tile only) ----
        if (kt == qt) {
            const int rbase = wid * 16 + (lane >> 2);
            const int cb = 2 * (lane & 3);
#pragma unroll
            for (int oct = 0; oct < 16; ++oct) {
                int c0 = oct * 8 + cb;
                if (c0     > rbase)     sc[oct][0] = -1e9f;
                if (c0 + 1 > rbase)     sc[oct][1] = -1e9f;
                if (c0     > rbase + 8) sc[oct][2] = -1e9f;
                if (c0 + 1 > rbase + 8) sc[oct][3] = -1e9f;
            }
        }

        // ---- online softmax (rows fully warp-local: lanes 4r..4r+3) ----
#pragma unroll
        for (int r = 0; r < 2; ++r) {
            float mx = -INFINITY;
#pragma unroll
            for (int oct = 0; oct < 16; ++oct)
                mx = fmaxf(mx, fmaxf(sc[oct][2 * r], sc[oct][2 * r + 1]));
            mx = fmaxf(mx, __shfl_xor_sync(0xffffffffu, mx, 1));
            mx = fmaxf(mx, __shfl_xor_sync(0xffffffffu, mx, 2));
            float mnew = fmaxf(mr[r], mx);
            float corr = __expf(mr[r] - mnew);
            mr[r] = mnew;
            float sum = 0.f;
#pragma unroll
            for (int oct = 0; oct < 16; ++oct) {
                float p0 = __expf(sc[oct][2 * r]     - mnew);
                float p1 = __expf(sc[oct][2 * r + 1] - mnew);
                sc[oct][2 * r] = p0; sc[oct][2 * r + 1] = p1;
                sum += p0 + p1;
            }
            sum += __shfl_xor_sync(0xffffffffu, sum, 1);
            sum += __shfl_xor_sync(0xffffffffu, sum, 2);
            lr[r] = lr[r] * corr + sum;
#pragma unroll
            for (int d = 0; d < 8; ++d) {
                o[d][2 * r] *= corr; o[d][2 * r + 1] *= corr;
            }
        }

        // ---- O += P @ V (3-pass split; P from registers) ----
        // A-frag order per PTX m16n8k16: {r0 k0-7, r8 k0-7, r0 k8-15, r8 k8-15}
        // = {oct0[0,1], oct0[2,3], oct1[0,1], oct1[2,3]} — natural order, no swap.
#pragma unroll
        for (int kf = 0; kf < 8; ++kf) {
            uint32_t pah[4], pal[4];
#pragma unroll
            for (int q2 = 0; q2 < 2; ++q2) {
                const float* p = sc[2 * kf + q2];
                uint32_t h0 = packbf2(p[0], p[1]);
                pal[2 * q2]     = packbf2(p[0] - lowf(h0), p[1] - highf(h0));
                pah[2 * q2]     = h0;
                uint32_t h1 = packbf2(p[2], p[3]);
                pal[2 * q2 + 1] = packbf2(p[2] - lowf(h1), p[3] - highf(h1));
                pah[2 * q2 + 1] = h1;
            }

            const uint32_t lm = (uint32_t)((lane & 15) * VP + kf * 16
                                           + (lane >> 4) * 8) * 2;
#pragma unroll
            for (int g = 0; g < 4; ++g) {
                uint32_t vb[4], vl[4];
                uint32_t ro = (uint32_t)(g * 16 * VP) * 2;
                ldm_x4(vb, stg + 2 * AQ_B + ro + lm);
                ldm_x4(vl, stg + 2 * AQ_B + AVT_B + ro + lm);
#pragma unroll
                for (int hf = 0; hf < 2; ++hf) {
                    const int oct = g * 2 + hf;
                    mma16816(o[oct], pah, vb[hf], vb[hf + 2]);
                    mma16816(o[oct], pah, vl[hf], vl[hf + 2]);
                    mma16816(o[oct], pal, vb[hf], vb[hf + 2]);
                }
            }
        }
    }

    // ---- epilogue: O/l -> bf16 hi/lo into GEMM A-layout [m, h*64+d] ----
    const float inv0 = 1.f / lr[0], inv1 = 1.f / lr[1];
    const int row0 = qbase + wid * 16 + (lane >> 2);
    const size_t m0 = (size_t)b * SEQ + row0;
#pragma unroll
    for (int oct = 0; oct < 8; ++oct) {
        const int col = h * DH + oct * 8 + 2 * (lane & 3);
        float v00 = o[oct][0] * inv0, v01 = o[oct][1] * inv0;
        float v10 = o[oct][2] * inv1, v11 = o[oct][3] * inv1;
        uint32_t h2 = packbf2(v00, v01);
        uint32_t l2 = packbf2(v00 - lowf(h2), v01 - highf(h2));
        *(uint32_t*)&Ahi[m0 * DM + col] = h2;
        *(uint32_t*)&Alo[m0 * DM + col] = l2;
        h2 = packbf2(v10, v11);
        l2 = packbf2(v10 - lowf(h2), v11 - highf(h2));
        *(uint32_t*)&Ahi[(m0 + 8) * DM + col] = h2;
        *(uint32_t*)&Alo[(m0 + 8) * DM + col] = l2;
    }
}

// ---------------------------------------------------------------------------
extern "C" void kernel_launch(void* const* d_in, const int* in_sizes, int n_in,
                              void* d_out, int out_size)
{
    (void)in_sizes; (void)n_in; (void)out_size;
    const float* q  = (const float*)d_in[0];
    const float* k  = (const float*)d_in[1];
    const float* v  = (const float*)d_in[2];
    const float* wq = (const float*)d_in[3];
    const float* bq = (const float*)d_in[4];
    const float* wk = (const float*)d_in[5];
    const float* bk = (const float*)d_in[6];
    const float* wv = (const float*)d_in[7];
    const float* bv = (const float*)d_in[8];
    const float* wo = (const float*)d_in[9];
    const float* bo = (const float*)d_in[10];
    float* out = (float*)d_out;

    __nv_bfloat16 *qhi, *qlo, *khi, *klo, *vthi, *vtlo, *ahi, *alo, *whi, *wlo;
    cudaGetSymbolAddress((void**)&qhi,  g_qhi);
    cudaGetSymbolAddress((void**)&qlo,  g_qlo);
    cudaGetSymbolAddress((void**)&khi,  g_khi);
    cudaGetSymbolAddress((void**)&klo,  g_klo);
    cudaGetSymbolAddress((void**)&vthi, g_vthi);
    cudaGetSymbolAddress((void**)&vtlo, g_vtlo);
    cudaGetSymbolAddress((void**)&ahi,  g_ahi);
    cudaGetSymbolAddress((void**)&alo,  g_alo);
    cudaGetSymbolAddress((void**)&whi,  g_whi);
    cudaGetSymbolAddress((void**)&wlo,  g_wlo);

    cudaFuncSetAttribute(gemm_mma<0>, cudaFuncAttributeMaxDynamicSharedMemorySize, GSMEM_B);
    cudaFuncSetAttribute(gemm_mma<1>, cudaFuncAttributeMaxDynamicSharedMemorySize, GSMEM_B);
    cudaFuncSetAttribute(gemm_mma<2>, cudaFuncAttributeMaxDynamicSharedMemorySize, GSMEM_B);
    cudaFuncSetAttribute(attn_mma,    cudaFuncAttributeMaxDynamicSharedMemorySize, ASM_B);

    const int M = BATCH * SEQ;                  // 4096
    const int n4A = M * DM / 4;
    dim3 cg(n4A / 256);
    dim3 wg(DM / 32, DM / 32);
    dim3 gg(DM / 128, M / 128);

    // Q projection -> bf16 hi/lo head layout
    convW<<<wg, 256>>>(wq, whi, wlo);
    convA<<<cg, 256>>>((const float4*)q, ahi, alo, n4A);
    gemm_mma<1><<<gg, 256, GSMEM_B>>>(ahi, alo, whi, wlo, bq, nullptr, qhi, qlo);
    // K projection
    convW<<<wg, 256>>>(wk, whi, wlo);
    convA<<<cg, 256>>>((const float4*)k, ahi, alo, n4A);
    gemm_mma<1><<<gg, 256, GSMEM_B>>>(ahi, alo, whi, wlo, bk, nullptr, khi, klo);
    // V projection -> transposed [b,h,d,s]
    convW<<<wg, 256>>>(wv, whi, wlo);
    convA<<<cg, 256>>>((const float4*)v, ahi, alo, n4A);
    gemm_mma<2><<<gg, 256, GSMEM_B>>>(ahi, alo, whi, wlo, bv, nullptr, vthi, vtlo);

    // attention (mma.sync, split-bf16) -> writes ahi/alo for output GEMM
    attn_mma<<<dim3(SEQ / 128, NH, BATCH), 256, ASM_B>>>(
        qhi, qlo, khi, klo, vthi, vtlo, ahi, alo);

    // output projection (fp32 out)
    convW<<<wg, 256>>>(wo, whi, wlo);
    gemm_mma<0><<<gg, 256, GSMEM_B>>>(ahi, alo, whi, wlo, bo, out, nullptr, nullptr);
}